// round 1
// baseline (speedup 1.0000x reference)
#include <cuda_runtime.h>
#include <math.h>

#define BATCH 256
#define NI    1152
#define NO    10
#define DOUT  16
#define DIN   8
#define OD    160          // NO * DOUT

// ---------------- scratch (device globals; no allocation) ----------------
__device__ float g_xhat[(size_t)BATCH * NI * OD];   // [b][i][o*16+d]  fp32, 189MB
__device__ float g_spart[72 * BATCH * OD];          // per-i-tile partial sums of xhat
__device__ float g_out0[BATCH * OD];                // squash(0.1 * sum_i xhat)

// =====================================================================
// Kernel 1: x_hat[b,i,o,d] = sum_c W[o,i,d,c] * x[b,i,c]
//   also accumulates S_partial[i_tile][b][od] = sum_{i in tile} x_hat
// Tiling: CTA = 32 batches x 16 i's. Weight tile transposed into SMEM as
// Ws[i][c][od] (padded) so each lane reads its od-quarter as float4.
// =====================================================================
#define K1_BT 32
#define K1_IT 16
#define WPAD  164
#define K1_SMEM ((K1_IT*8*WPAD + K1_BT*K1_IT*DIN) * 4)

__global__ __launch_bounds__(512) void k1_xhat(const float* __restrict__ x,
                                               const float* __restrict__ w)
{
    extern __shared__ float sm[];
    float* Ws = sm;                          // [16][8][WPAD]
    float* xs = sm + K1_IT * 8 * WPAD;       // [32][128]

    const int i0 = blockIdx.x * K1_IT;
    const int b0 = blockIdx.y * K1_BT;
    const int tid = threadIdx.x;

    // --- load weight tile, transposed: W[o][i0+il][d][c] -> Ws[il][c][o*16+d]
    for (int idx = tid; idx < NO * K1_IT * 128; idx += 512) {
        int o   = idx / (K1_IT * 128);
        int r   = idx % (K1_IT * 128);
        int il  = r >> 7;
        int rem = r & 127;                   // d*8 + c
        int d   = rem >> 3;
        int c   = rem & 7;
        float v = w[((size_t)(o * NI + i0 + il)) * 128 + rem];
        Ws[il * (8 * WPAD) + c * WPAD + o * 16 + d] = v;
    }
    // --- load x tile: x[b0+bl][i0..i0+15][c]
    for (int idx = tid; idx < K1_BT * K1_IT * DIN; idx += 512) {
        int bl = idx >> 7;
        int r  = idx & 127;
        xs[bl * 128 + r] = x[(size_t)(b0 + bl) * (NI * DIN) + (size_t)i0 * DIN + r];
    }
    __syncthreads();

    const int warp = tid >> 5;
    const int lane = tid & 31;

    // warp handles 2 batches x 16 i's; lane owns od in {4l..4l+3, 128+l}
    for (int bb = 0; bb < 2; bb++) {
        const int bl = warp * 2 + bb;
        float4 sa = make_float4(0.f, 0.f, 0.f, 0.f);
        float  sa4 = 0.f;
        const float* xr0 = &xs[bl * 128];
        for (int ii = 0; ii < K1_IT; ii++) {
            float4 a = make_float4(0.f, 0.f, 0.f, 0.f);
            float  a4 = 0.f;
            const float* xr = xr0 + ii * 8;
            const float* wr = &Ws[ii * (8 * WPAD)];
            #pragma unroll
            for (int c = 0; c < 8; c++) {
                float xc = xr[c];                         // broadcast LDS
                float4 wv = *(const float4*)&wr[c * WPAD + 4 * lane];
                float  w4 = wr[c * WPAD + 128 + lane];
                a.x = fmaf(wv.x, xc, a.x);
                a.y = fmaf(wv.y, xc, a.y);
                a.z = fmaf(wv.z, xc, a.z);
                a.w = fmaf(wv.w, xc, a.w);
                a4  = fmaf(w4,  xc, a4);
            }
            size_t base = ((size_t)(b0 + bl) * NI + (i0 + ii)) * OD;
            *(float4*)&g_xhat[base + 4 * lane] = a;
            g_xhat[base + 128 + lane] = a4;
            sa.x += a.x; sa.y += a.y; sa.z += a.z; sa.w += a.w; sa4 += a4;
        }
        size_t sb = ((size_t)blockIdx.x * BATCH + (b0 + bl)) * OD;
        *(float4*)&g_spart[sb + 4 * lane] = sa;
        g_spart[sb + 128 + lane] = sa4;
    }
}

// =====================================================================
// Kernel 2: reduce partials -> s0 = 0.1 * sum_i x_hat; out0 = squash(s0)
// grid 256 (b), block 160 (od). Squash norm over 16 d via shfl.
// =====================================================================
__global__ void k2_out0()
{
    const int b  = blockIdx.x;
    const int od = threadIdx.x;     // 0..159
    float s = 0.f;
    #pragma unroll 8
    for (int k = 0; k < 72; k++)
        s += g_spart[((size_t)k * BATCH + b) * OD + od];
    s *= 0.1f;
    float v = s * s;
    v += __shfl_xor_sync(0xffffffffu, v, 8);
    v += __shfl_xor_sync(0xffffffffu, v, 4);
    v += __shfl_xor_sync(0xffffffffu, v, 2);
    v += __shfl_xor_sync(0xffffffffu, v, 1);
    float out = s * (v / (1.0f + v)) / (sqrtf(v) + 1e-8f);
    g_out0[b * OD + od] = out;
}

// =====================================================================
// Kernel 3: routing iterations 1 and 2, one CTA per batch.
//   Pass A: t=out0;       logits b1 = <t, xh_i>, c=softmax_o, s1=sum c*xh
//           out1 = squash(s1); t += out1
//   Pass B: logits b2 = <t, xh_i>, c=softmax_o, s2=sum c*xh
//           output = squash(s2)
// 256 threads = 64 groups of 4 lanes; lane j owns d-quarter [4j,4j+4).
// xh for the current i stays in registers between the logit dot and the
// s-accumulation (one global read per pass).
// =====================================================================
__global__ __launch_bounds__(256, 1) void k3_route(float* __restrict__ dout)
{
    __shared__ float4 red[8][4][NO];  // [warp][j][o]
    __shared__ float  smem_t[OD];

    const int b    = blockIdx.x;
    const int tid  = threadIdx.x;
    const int lane = tid & 31;
    const int warp = tid >> 5;
    const int g    = tid >> 2;        // 0..63
    const int j    = tid & 3;

    if (tid < OD) smem_t[tid] = g_out0[b * OD + tid];
    __syncthreads();

    for (int pass = 0; pass < 2; pass++) {
        float4 t4[NO];
        #pragma unroll
        for (int o = 0; o < NO; o++)
            t4[o] = *(const float4*)&smem_t[o * 16 + 4 * j];

        float4 acc[NO];
        #pragma unroll
        for (int o = 0; o < NO; o++) acc[o] = make_float4(0.f, 0.f, 0.f, 0.f);

        for (int k = 0; k < 18; k++) {
            const int i = g + 64 * k;
            const size_t base = ((size_t)b * NI + i) * OD + 4 * j;
            float4 xh[NO];
            #pragma unroll
            for (int o = 0; o < NO; o++)
                xh[o] = *(const float4*)&g_xhat[base + o * 16];

            float e[NO];
            #pragma unroll
            for (int o = 0; o < NO; o++) {
                float p = xh[o].x * t4[o].x;
                p = fmaf(xh[o].y, t4[o].y, p);
                p = fmaf(xh[o].z, t4[o].z, p);
                p = fmaf(xh[o].w, t4[o].w, p);
                p += __shfl_xor_sync(0xffffffffu, p, 1);
                p += __shfl_xor_sync(0xffffffffu, p, 2);
                e[o] = p;                          // full logit for this (i,o)
            }
            float m = e[0];
            #pragma unroll
            for (int o = 1; o < NO; o++) m = fmaxf(m, e[o]);
            float sum = 0.f;
            #pragma unroll
            for (int o = 0; o < NO; o++) { e[o] = __expf(e[o] - m); sum += e[o]; }
            const float inv = 1.0f / sum;
            #pragma unroll
            for (int o = 0; o < NO; o++) {
                float c = e[o] * inv;
                acc[o].x = fmaf(c, xh[o].x, acc[o].x);
                acc[o].y = fmaf(c, xh[o].y, acc[o].y);
                acc[o].z = fmaf(c, xh[o].z, acc[o].z);
                acc[o].w = fmaf(c, xh[o].w, acc[o].w);
            }
        }

        // reduce across the 8 groups within each warp (same role j every 4 lanes)
        #pragma unroll
        for (int o = 0; o < NO; o++) {
            #pragma unroll
            for (int msk = 4; msk <= 16; msk <<= 1) {
                acc[o].x += __shfl_xor_sync(0xffffffffu, acc[o].x, msk);
                acc[o].y += __shfl_xor_sync(0xffffffffu, acc[o].y, msk);
                acc[o].z += __shfl_xor_sync(0xffffffffu, acc[o].z, msk);
                acc[o].w += __shfl_xor_sync(0xffffffffu, acc[o].w, msk);
            }
        }
        if (lane < 4) {
            #pragma unroll
            for (int o = 0; o < NO; o++) red[warp][lane][o] = acc[o];
        }
        __syncthreads();

        if (tid < OD) {
            const int od = tid;
            const int o  = od >> 4;
            const int dl = od & 15;
            const int jj = dl >> 2;
            const int dd = dl & 3;
            float s = 0.f;
            #pragma unroll
            for (int w8 = 0; w8 < 8; w8++)
                s += ((const float*)&red[w8][jj][o])[dd];
            // squash over the 16 d's of this o (lanes [o*16, o*16+16))
            float v = s * s;
            v += __shfl_xor_sync(0xffffffffu, v, 8);
            v += __shfl_xor_sync(0xffffffffu, v, 4);
            v += __shfl_xor_sync(0xffffffffu, v, 2);
            v += __shfl_xor_sync(0xffffffffu, v, 1);
            float out = s * (v / (1.0f + v)) / (sqrtf(v) + 1e-8f);
            if (pass == 0) smem_t[od] += out;            // t = out0 + out1
            else           dout[b * OD + od] = out;      // final [B,O,Dout]
        }
        __syncthreads();
    }
}

// =====================================================================
extern "C" void kernel_launch(void* const* d_in, const int* in_sizes, int n_in,
                              void* d_out, int out_size)
{
    const float* x = (const float*)d_in[0];   // [256,1152,8]
    const float* w = (const float*)d_in[1];   // [10,1152,16,8]
    float* out = (float*)d_out;               // [256,10,16]

    cudaFuncSetAttribute(k1_xhat, cudaFuncAttributeMaxDynamicSharedMemorySize, K1_SMEM);

    k1_xhat<<<dim3(NI / K1_IT, BATCH / K1_BT), 512, K1_SMEM>>>(x, w);
    k2_out0<<<BATCH, OD>>>();
    k3_route<<<BATCH, 256>>>(out);
}